// round 7
// baseline (speedup 1.0000x reference)
#include <cuda_runtime.h>
#include <math.h>

#define W    512
#define HGT  512
#define HW   (512*512)
#define TW   64
#define TH   64
#define RMAX 10
#define SW   84               // TW + 2*RMAX
#define SH   (TH + 2*RMAX)    // 84
#define MWP  66               // mid row stride in u64 (66*8B=528B -> conflict-free 16B stores)
#define NTH  256
#define NPASS 11
#define WSUM 123
#define SMEM_BYTES (SH*SW*4 + SH*MWP*8 + WSUM*8)

typedef unsigned long long u64;

// pass table: pairs of equal-K filters (filter i has K=KS[i], sigma=0.5+0.025i)
__constant__ int P_FA[NPASS]  = {0,3,5,7,9,11,13,15,17,19,2};
__constant__ int P_FB[NPASS]  = {1,4,6,8,10,12,14,16,18,20,2};
__constant__ int P_K [NPASS]  = {3,5,7,9,11,13,15,17,19,21,3};
__constant__ int P_OFF[NPASS] = {0,3,8,15,24,35,48,63,80,99,120};

__device__ __forceinline__ u64 pack2(float lo, float hi) {
    u64 d; asm("mov.b64 %0, {%1, %2};" : "=l"(d) : "f"(lo), "f"(hi)); return d;
}
__device__ __forceinline__ void fma2(u64& d, u64 a, u64 b) {
    asm("fma.rn.f32x2 %0, %1, %2, %0;" : "+l"(d) : "l"(a), "l"(b));
}
union F2 { u64 u; float2 f; };

__device__ __forceinline__ int refl(int v) {
    if (v < 0)    v = -v;
    if (v >= 512) v = 1022 - v;
    return v;
}

// One pass = two same-K filters packed in f32x2 lanes (lo=filter A, hi=filter B).
template<int K>
__device__ __forceinline__ void blur_pair(const float* __restrict__ s_in,
                                          u64* __restrict__ midp,
                                          const u64* __restrict__ w2,
                                          float* __restrict__ outA,
                                          float* __restrict__ outB,
                                          bool dualB,
                                          int x0, int y0, int tid) {
    constexpr int R     = (K - 1) / 2;
    constexpr int MROWS = TH + 2 * R;        // <= 84
    constexpr int HK    = (K + 1) / 2;
    constexpr int D     = (RMAX - R) & 3;
    constexpr int COL0  = (RMAX - R) - D;
    constexpr int ROW0  = RMAX - R;
    constexpr int NV    = D + K + 15;
    constexpr int NW4   = (NV + 3) / 4;

    u64 wr[HK];
    #pragma unroll
    for (int j = 0; j < HK; ++j) wr[j] = w2[j];

    // ---- horizontal: 1 mid row x 16 cols per task; pixel duplicated, filters packed ----
    {
        int lane = tid & 31, wid = tid >> 5;
        int lr = lane & 7, cg = lane >> 3;   // row-in-chunk, 16-col group (0..3)
        constexpr int NCH = (MROWS + 7) / 8;
        for (int ch = wid; ch < NCH; ch += 8) {
            int r = ch * 8 + lr;
            if (r < MROWS) {
                const float4* src = (const float4*)(s_in + (r + ROW0) * SW + cg * 16 + COL0);
                float vb[8];
                *(float4*)&vb[0] = src[0];
                *(float4*)&vb[4] = src[1];
                u64 a[16];
                #pragma unroll
                for (int c = 0; c < 16; ++c) a[c] = 0;
                #pragma unroll
                for (int m = 0; m < K + 15; ++m) {
                    int e = D + m;
                    if (e >= 8 && (e & 3) == 0)
                        *(float4*)&vb[((e >> 2) & 1) * 4] = src[e >> 2];
                    u64 p = pack2(vb[e & 7], vb[e & 7]);
                    #pragma unroll
                    for (int c = 0; c < 16; ++c) {
                        int j = m - c;
                        if (j >= 0 && j < K)
                            fma2(a[c], wr[(j < HK) ? j : (K - 1 - j)], p);
                    }
                }
                u64* dst = midp + r * MWP + cg * 16;
                #pragma unroll
                for (int c = 0; c < 16; c += 2)
                    *(ulonglong2*)(dst + c) = make_ulonglong2(a[c], a[c + 1]);
            }
        }
    }
    __syncthreads();

    // ---- vertical: 16 rows x 1 col per thread; both filters in the u64 lanes ----
    {
        int col = tid & 63, rg = tid >> 6;   // 64 cols x 4 row-groups
        int r0 = rg * 16;
        const u64* mp = midp + r0 * MWP + col;
        u64 acc[16];
        #pragma unroll
        for (int r = 0; r < 16; ++r) acc[r] = 0;
        #pragma unroll
        for (int m = 0; m < K + 15; ++m) {
            u64 val = mp[m * MWP];
            #pragma unroll
            for (int r = 0; r < 16; ++r) {
                int j = m - r;
                if (j >= 0 && j < K)
                    fma2(acc[r], wr[(j < HK) ? j : (K - 1 - j)], val);
            }
        }
        float* oa = outA + (size_t)(y0 + r0) * W + (x0 + col);
        float* ob = outB + (size_t)(y0 + r0) * W + (x0 + col);
        if (dualB) {
            #pragma unroll
            for (int r = 0; r < 16; ++r) {
                F2 f; f.u = acc[r];
                oa[(size_t)r * W] = f.f.x;
                ob[(size_t)r * W] = f.f.y;
            }
        } else {
            #pragma unroll
            for (int r = 0; r < 16; ++r) {
                F2 f; f.u = acc[r];
                oa[(size_t)r * W] = f.f.x;
            }
        }
    }
    __syncthreads();
}

__global__ void __launch_bounds__(NTH, 3)
gauss_fused(const float* __restrict__ x, float* __restrict__ out) {
    extern __shared__ float smem[];
    float* s_in = smem;                          // SH*SW floats
    u64*   midp = (u64*)(smem + SH * SW);        // SH*MWP u64
    u64*   s_w2 = midp + SH * MWP;               // WSUM packed weight pairs

    int tid = threadIdx.x;

    // per-pass paired weight generation (graph-capturable)
    if (tid < NPASS) {
        int K = P_K[tid];
        int fa = P_FA[tid], fb = P_FB[tid];
        int off = P_OFF[tid];
        float sa = 0.5f + 0.025f * fa;
        float sb = 0.5f + 0.025f * fb;
        float s2a = 2.0f * sa * sa, s2b = 2.0f * sb * sb;
        int h = K / 2;
        float suma = 0.0f, sumb = 0.0f;
        for (int j = 0; j < K; ++j) {
            float d = (float)(j - h);
            suma += expf(-d * d / s2a);
            sumb += expf(-d * d / s2b);
        }
        for (int j = 0; j < K; ++j) {
            float d = (float)(j - h);
            float wa = expf(-d * d / s2a) / suma;
            float wb = expf(-d * d / s2b) / sumb;
            s_w2[off + j] = pack2(wa, wb);
        }
    }

    int z = blockIdx.z;                 // b*3 + c
    int b = z / 3, c = z - 3 * b;
    int x0 = blockIdx.x * TW, y0 = blockIdx.y * TH;
    const float* xin = x + (size_t)z * HW;

    // load 84x84 halo tile once, reused by all passes
    bool interior = (x0 != 0) && (x0 != W - TW) && (y0 != 0) && (y0 != HGT - TH);
    if (interior) {
        const float* base = xin + (size_t)(y0 - RMAX) * W + (x0 - RMAX);
        for (int idx = tid; idx < SH * (SW / 2); idx += NTH) {
            int ly = idx / (SW / 2), lx = idx - ly * (SW / 2);
            *(float2*)(s_in + ly * SW + lx * 2) =
                *(const float2*)(base + ly * W + lx * 2);
        }
    } else {
        for (int idx = tid; idx < SH * SW; idx += NTH) {
            int ly = idx / SW, lx = idx - ly * SW;
            int gy = refl(y0 + ly - RMAX);
            int gx = refl(x0 + lx - RMAX);
            s_in[idx] = xin[gy * W + gx];
        }
    }
    __syncthreads();

    #pragma unroll 1
    for (int p = 0; p < NPASS; ++p) {
        int fa = P_FA[p], fb = P_FB[p];
        float* oA = out + (size_t)(b * 66 + 3 + 3 * fa + c) * HW;
        float* oB = out + (size_t)(b * 66 + 3 + 3 * fb + c) * HW;
        bool dualB = (fb != fa);
        const u64* w2 = s_w2 + P_OFF[p];
        switch (P_K[p]) {
            case 3:  blur_pair<3 >(s_in, midp, w2, oA, oB, dualB, x0, y0, tid); break;
            case 5:  blur_pair<5 >(s_in, midp, w2, oA, oB, dualB, x0, y0, tid); break;
            case 7:  blur_pair<7 >(s_in, midp, w2, oA, oB, dualB, x0, y0, tid); break;
            case 9:  blur_pair<9 >(s_in, midp, w2, oA, oB, dualB, x0, y0, tid); break;
            case 11: blur_pair<11>(s_in, midp, w2, oA, oB, dualB, x0, y0, tid); break;
            case 13: blur_pair<13>(s_in, midp, w2, oA, oB, dualB, x0, y0, tid); break;
            case 15: blur_pair<15>(s_in, midp, w2, oA, oB, dualB, x0, y0, tid); break;
            case 17: blur_pair<17>(s_in, midp, w2, oA, oB, dualB, x0, y0, tid); break;
            case 19: blur_pair<19>(s_in, midp, w2, oA, oB, dualB, x0, y0, tid); break;
            case 21: blur_pair<21>(s_in, midp, w2, oA, oB, dualB, x0, y0, tid); break;
        }
    }
}

// identity channels: out[b][0..2] = x[b][0..2]
__global__ void copy_id(const float* __restrict__ x, float* __restrict__ out) {
    int plane = blockIdx.y;             // b*3 + c
    int b = plane / 3, c = plane - 3 * b;
    const float4* src = (const float4*)(x + (size_t)plane * HW);
    float4*       dst = (float4*)(out + (size_t)(b * 66 + c) * HW);
    int i = blockIdx.x * blockDim.x + threadIdx.x;
    dst[i] = src[i];
}

extern "C" void kernel_launch(void* const* d_in, const int* in_sizes, int n_in,
                              void* d_out, int out_size) {
    const float* x = (const float*)d_in[0];
    float* out = (float*)d_out;

    cudaFuncSetAttribute(gauss_fused, cudaFuncAttributeMaxDynamicSharedMemorySize, SMEM_BYTES);

    dim3 cgrid(HW / 4 / NTH, 24);
    copy_id<<<cgrid, NTH>>>(x, out);

    dim3 grid(W / TW, HGT / TH, 24);    // 8 x 8 x 24
    gauss_fused<<<grid, NTH, SMEM_BYTES>>>(x, out);
}

// round 8
// speedup vs baseline: 1.0807x; 1.0807x over previous
#include <cuda_runtime.h>
#include <math.h>

#define W    512
#define HGT  512
#define HW   (512*512)
#define TW   64
#define TH   64
#define RMAX 10
#define SW   84
#define SH   84
#define MWP  66               // mid row stride in u64
#define NTH  256
#define NPASS 11
#define WSUM 123
#define SMEM_BYTES (SH*SW*4 + SH*MWP*8 + WSUM*8)

typedef unsigned long long u64;

// pass table: pairs of equal-K filters (filter i has K=KS[i], sigma=0.5+0.025i)
__constant__ int P_FA[NPASS]  = {0,3,5,7,9,11,13,15,17,19,2};
__constant__ int P_FB[NPASS]  = {1,4,6,8,10,12,14,16,18,20,2};
__constant__ int P_K [NPASS]  = {3,5,7,9,11,13,15,17,19,21,3};
__constant__ int P_OFF[NPASS] = {0,3,8,15,24,35,48,63,80,99,120};

__device__ __forceinline__ u64 pack2(float lo, float hi) {
    u64 d; asm("mov.b64 %0, {%1, %2};" : "=l"(d) : "f"(lo), "f"(hi)); return d;
}
__device__ __forceinline__ void fma2(u64& d, u64 a, u64 b) {
    asm("fma.rn.f32x2 %0, %1, %2, %0;" : "+l"(d) : "l"(a), "l"(b));
}
union F2 { u64 u; float2 f; };

__device__ __forceinline__ int refl(int v) {
    if (v < 0)    v = -v;
    if (v >= 512) v = 1022 - v;
    return v;
}

// One pass = two same-K filters packed in f32x2 lanes. Fully warp-local:
// this warp computes mid for its 8 columns, then V from its own mid. No barriers.
template<int K>
__device__ __forceinline__ void blur_pair(const float* __restrict__ s_in,
                                          u64* __restrict__ midp,
                                          const u64* __restrict__ w2,
                                          float* __restrict__ outA,
                                          float* __restrict__ outB,
                                          bool dualB,
                                          int x0, int y0, int lane, int c0) {
    constexpr int R     = (K - 1) / 2;
    constexpr int MROWS = TH + 2 * R;          // 66..84
    constexpr int HK    = (K + 1) / 2;
    constexpr int D     = (RMAX - R) & 3;
    constexpr int COL0  = (RMAX - R) - D;
    constexpr int ROW0  = RMAX - R;
    constexpr int NW4   = (D + K + 10) >> 2;   // float4 chunks needed

    u64 wr[HK];
    #pragma unroll
    for (int j = 0; j < HK; ++j) wr[j] = w2[j];

    // ---- horizontal: warp covers rows 0..MROWS-1 of its 8 columns ----
    #pragma unroll
    for (int rb = 0; rb < 96; rb += 32) {
        int r = rb + lane;
        bool act = (rb + 32 <= MROWS) || (r < MROWS);
        if (act) {
            const float4* src = (const float4*)(s_in + (r + ROW0) * SW + (c0 + COL0));
            float vb[16];
            *(float4*)&vb[0]  = src[0];
            *(float4*)&vb[4]  = src[1];
            *(float4*)&vb[8]  = src[2];
            *(float4*)&vb[12] = src[3];
            u64 a[8];
            #pragma unroll
            for (int g = 0; g < 8; ++g) a[g] = 0;
            #pragma unroll
            for (int e = D; e < D + K + 7; ++e) {
                if ((e & 3) == 0) {
                    int ch = (e >> 2) + 2;
                    if (ch >= 4 && ch < NW4)
                        *(float4*)&vb[(ch & 3) * 4] = src[ch];
                }
                u64 p = pack2(vb[e & 15], vb[e & 15]);
                #pragma unroll
                for (int g = 0; g < 8; ++g) {
                    int j = e - D - g;
                    if (j >= 0 && j < K)
                        fma2(a[g], wr[(j < HK) ? j : (K - 1 - j)], p);
                }
            }
            u64* dst = midp + r * MWP + ((c0 + 8 * (r >> 4)) & 63);
            *(ulonglong2*)(dst + 0) = make_ulonglong2(a[0], a[1]);
            *(ulonglong2*)(dst + 2) = make_ulonglong2(a[2], a[3]);
            *(ulonglong2*)(dst + 4) = make_ulonglong2(a[4], a[5]);
            *(ulonglong2*)(dst + 6) = make_ulonglong2(a[6], a[7]);
        }
    }
    __syncwarp();

    // ---- vertical: lane = (c 0..7, rg 0..3), 16 rows x 1 col each ----
    {
        int c  = lane & 7, rg = lane >> 3;
        int r0 = rg << 4;
        int colA = (c0 + c + (rg << 3)) & 63;
        const u64* mbase = midp + r0 * MWP;
        u64 acc[16];
        #pragma unroll
        for (int rr = 0; rr < 16; ++rr) acc[rr] = 0;
        #pragma unroll
        for (int m = 0; m < K + 15; ++m) {
            int col = (m < 16) ? colA : ((m < 32) ? ((colA + 8) & 63) : ((colA + 16) & 63));
            u64 val = mbase[m * MWP + col];
            #pragma unroll
            for (int rr = 0; rr < 16; ++rr) {
                int j = m - rr;
                if (j >= 0 && j < K)
                    fma2(acc[rr], wr[(j < HK) ? j : (K - 1 - j)], val);
            }
        }
        float* oa = outA + (size_t)(y0 + r0) * W + (x0 + c0 + c);
        float* ob = outB + (size_t)(y0 + r0) * W + (x0 + c0 + c);
        if (dualB) {
            #pragma unroll
            for (int rr = 0; rr < 16; ++rr) {
                F2 f; f.u = acc[rr];
                oa[(size_t)rr * W] = f.f.x;
                ob[(size_t)rr * W] = f.f.y;
            }
        } else {
            #pragma unroll
            for (int rr = 0; rr < 16; ++rr) {
                F2 f; f.u = acc[rr];
                oa[(size_t)rr * W] = f.f.x;
            }
        }
    }
    __syncwarp();
}

__global__ void __launch_bounds__(NTH, 3)
gauss_fused(const float* __restrict__ x, float* __restrict__ out) {
    extern __shared__ float smem[];
    float* s_in = smem;                          // SH*SW floats
    u64*   midp = (u64*)(smem + SH * SW);        // SH*MWP u64 (rotated layout)
    u64*   s_w2 = midp + SH * MWP;               // WSUM weight pairs

    int tid = threadIdx.x;

    // per-pass paired weight generation (graph-capturable)
    if (tid < NPASS) {
        int K = P_K[tid];
        int fa = P_FA[tid], fb = P_FB[tid];
        int off = P_OFF[tid];
        float sa = 0.5f + 0.025f * fa;
        float sb = 0.5f + 0.025f * fb;
        float s2a = 2.0f * sa * sa, s2b = 2.0f * sb * sb;
        int h = K / 2;
        float suma = 0.0f, sumb = 0.0f;
        for (int j = 0; j < K; ++j) {
            float d = (float)(j - h);
            suma += expf(-d * d / s2a);
            sumb += expf(-d * d / s2b);
        }
        for (int j = 0; j < K; ++j) {
            float d = (float)(j - h);
            s_w2[off + j] = pack2(expf(-d * d / s2a) / suma,
                                  expf(-d * d / s2b) / sumb);
        }
    }

    int z = blockIdx.z;                 // b*3 + c
    int b = z / 3, cch = z - 3 * b;
    int x0 = blockIdx.x * TW, y0 = blockIdx.y * TH;
    const float* xin = x + (size_t)z * HW;

    // load 84x84 halo tile once
    bool interior = (x0 != 0) && (x0 != W - TW) && (y0 != 0) && (y0 != HGT - TH);
    if (interior) {
        const float* base = xin + (size_t)(y0 - RMAX) * W + (x0 - RMAX);
        for (int idx = tid; idx < SH * (SW / 2); idx += NTH) {
            int ly = idx / (SW / 2), lx = idx - ly * (SW / 2);
            *(float2*)(s_in + ly * SW + lx * 2) =
                *(const float2*)(base + ly * W + lx * 2);
        }
    } else {
        for (int idx = tid; idx < SH * SW; idx += NTH) {
            int ly = idx / SW, lx = idx - ly * SW;
            int gy = refl(y0 + ly - RMAX);
            int gx = refl(x0 + lx - RMAX);
            s_in[idx] = xin[gy * W + gx];
        }
    }

    // identity channel: copy this tile of x into out[b*66+cch]
    {
        const float4* src = (const float4*)(xin + (size_t)y0 * W + x0);
        float4* dst = (float4*)(out + (size_t)(b * 66 + cch) * HW + (size_t)y0 * W + x0);
        #pragma unroll
        for (int i = tid; i < TH * (TW / 4); i += NTH) {
            int r = i >> 4, q = i & 15;
            dst[r * (W / 4) + q] = src[r * (W / 4) + q];
        }
    }
    __syncthreads();   // the ONLY block-wide barrier

    int lane = tid & 31;
    int c0 = (tid >> 5) * 8;            // warp's column slice

    #pragma unroll 1
    for (int p = 0; p < NPASS; ++p) {
        int fa = P_FA[p], fb = P_FB[p];
        float* oA = out + (size_t)(b * 66 + 3 + 3 * fa + cch) * HW;
        float* oB = out + (size_t)(b * 66 + 3 + 3 * fb + cch) * HW;
        bool dualB = (fb != fa);
        const u64* w2 = s_w2 + P_OFF[p];
        switch (P_K[p]) {
            case 3:  blur_pair<3 >(s_in, midp, w2, oA, oB, dualB, x0, y0, lane, c0); break;
            case 5:  blur_pair<5 >(s_in, midp, w2, oA, oB, dualB, x0, y0, lane, c0); break;
            case 7:  blur_pair<7 >(s_in, midp, w2, oA, oB, dualB, x0, y0, lane, c0); break;
            case 9:  blur_pair<9 >(s_in, midp, w2, oA, oB, dualB, x0, y0, lane, c0); break;
            case 11: blur_pair<11>(s_in, midp, w2, oA, oB, dualB, x0, y0, lane, c0); break;
            case 13: blur_pair<13>(s_in, midp, w2, oA, oB, dualB, x0, y0, lane, c0); break;
            case 15: blur_pair<15>(s_in, midp, w2, oA, oB, dualB, x0, y0, lane, c0); break;
            case 17: blur_pair<17>(s_in, midp, w2, oA, oB, dualB, x0, y0, lane, c0); break;
            case 19: blur_pair<19>(s_in, midp, w2, oA, oB, dualB, x0, y0, lane, c0); break;
            case 21: blur_pair<21>(s_in, midp, w2, oA, oB, dualB, x0, y0, lane, c0); break;
        }
    }
}

extern "C" void kernel_launch(void* const* d_in, const int* in_sizes, int n_in,
                              void* d_out, int out_size) {
    const float* x = (const float*)d_in[0];
    float* out = (float*)d_out;

    cudaFuncSetAttribute(gauss_fused, cudaFuncAttributeMaxDynamicSharedMemorySize, SMEM_BYTES);

    dim3 grid(W / TW, HGT / TH, 24);    // 8 x 8 x 24
    gauss_fused<<<grid, NTH, SMEM_BYTES>>>(x, out);
}